// round 10
// baseline (speedup 1.0000x reference)
#include <cuda_runtime.h>
#include <cstddef>

#define NB   8
#define NQ   100
#define SH   128
#define SW   128
#define OH   512
#define OW   512
#define QPI  4            // queries per iteration
#define NIT  (NQ / QPI)   // 25

__device__ __forceinline__ float fast_tanh(float x) {
    float r;
    asm("tanh.approx.f32 %0, %1;" : "=f"(r) : "f"(x));
    return r;
}

// Grid: (128 row-blocks k, 8 batches). Block: 512 threads, 3 CTAs/SM.
// Register-resident vertical lerp + shuffle-based horizontal neighbors.
// Thread role: ph = t>>7 (row phase), kx = t&127 (source column).
//   iter j: horizontal(quad j from vcur regs + edge[bs])
//        || vertical(quad j+1 from buf -> vnext regs, lane0/31 -> edge[nb])
//        || stage(quad j+2 -> buf[bs]);  ONE __syncthreads.
// buf layout [slot][row][col][e] -> vertical reads are 2x LDS.128.
// Data pre-halved; weights pre-halved; +Sum(w/2) folded at the end.
__global__ __launch_bounds__(512, 3)
void m2f_fused_kernel(const float* __restrict__ cls,
                      const float* __restrict__ masks,
                      float* __restrict__ out)
{
    const int k = blockIdx.x;
    const int b = blockIdx.y;
    const int t = threadIdx.x;

    __shared__ __align__(16) float buf[2][3][SW][QPI];   // staged rows, e-interleaved
    __shared__ __align__(16) float edge[2][16][2][QPI];  // [slot][warp][lo/hi][e]
    __shared__ __align__(16) float2 wts[NQ];
    __shared__ float2 wsum;

    const int lane = t & 31;
    const int w    = t >> 5;       // warp 0..15
    const int xb   = w & 3;        // x-block of warp within its phase
    const int ph   = t >> 7;       // row phase 0..3
    const int kx   = t & 127;      // source column

    // ---- per-CTA class softmax (halved) ----
    if (t < NQ) {
        const float* p = cls + ((size_t)b * NQ + t) * 3;
        float x0 = p[0], x1 = p[1], x2 = p[2];
        float m  = fmaxf(x0, fmaxf(x1, x2));
        float e0 = __expf(x0 - m), e1 = __expf(x1 - m), e2 = __expf(x2 - m);
        float inv = 0.5f / (e0 + e1 + e2);
        wts[t] = make_float2(e0 * inv, e1 * inv);
    }

    // clamped source rows
    const int r0 = (k == 0)      ? 0        : (k - 1);
    const int r2 = (k == SH - 1) ? (SH - 1) : (k + 1);
    const float* mb = masks + (size_t)b * NQ * SH * SW;
    const size_t qstride = (size_t)SH * SW;

    // staging role: 384 threads (warps 0..11), one float4 each
    const bool stager = (t < 384);
    const int  sq = w / 3;             // query-in-quad 0..3
    const int  rr = w % 3;             // row 0..2
    const int  c4 = t & 31;
    const int  stg_row = (rr == 0) ? r0 : ((rr == 1) ? k : r2);
    const float4* pf = reinterpret_cast<const float4*>(
        mb + (size_t)sq * qstride + (size_t)stg_row * SW) + c4;

    // vertical factors per phase
    const int ra   = (ph < 2) ? 0 : 1;
    const int rb   = ra + 1;
    const float vf = (ph == 0) ? 0.625f : (ph == 1) ? 0.875f
                   : (ph == 2) ? 0.125f : 0.375f;

    // ---- prologue: stage quad 0 ----
    if (stager) {
        float4 v = __ldg(pf);
        buf[0][rr][4*c4+0][sq] = 0.5f * v.x;
        buf[0][rr][4*c4+1][sq] = 0.5f * v.y;
        buf[0][rr][4*c4+2][sq] = 0.5f * v.z;
        buf[0][rr][4*c4+3][sq] = 0.5f * v.w;
        pf += qstride;   // float4 units: 4 queries ahead
    }
    __syncthreads();   // wts + buf[0] visible

    // weight sum (halved) by warp 0
    if (t < 32) {
        float sx = 0.f, sy = 0.f;
        for (int q = t; q < NQ; q += 32) { sx += wts[q].x; sy += wts[q].y; }
        #pragma unroll
        for (int o = 16; o > 0; o >>= 1) {
            sx += __shfl_down_sync(0xFFFFFFFFu, sx, o);
            sy += __shfl_down_sync(0xFFFFFFFFu, sy, o);
        }
        if (t == 0) wsum = make_float2(sx, sy);
    }

    // ---- prologue: vertical quad 0 -> vcur; stage quad 1 -> buf[1] ----
    float vcur[QPI];
    {
        float4 vg;
        if (stager) vg = __ldg(pf);

        float4 a  = *reinterpret_cast<const float4*>(&buf[0][ra][kx][0]);
        float4 bb = *reinterpret_cast<const float4*>(&buf[0][rb][kx][0]);
        vcur[0] = fmaf(vf, bb.x - a.x, a.x);
        vcur[1] = fmaf(vf, bb.y - a.y, a.y);
        vcur[2] = fmaf(vf, bb.z - a.z, a.z);
        vcur[3] = fmaf(vf, bb.w - a.w, a.w);
        if (lane == 0)
            *reinterpret_cast<float4*>(&edge[0][w][0][0])
                = make_float4(vcur[0], vcur[1], vcur[2], vcur[3]);
        if (lane == 31)
            *reinterpret_cast<float4*>(&edge[0][w][1][0])
                = make_float4(vcur[0], vcur[1], vcur[2], vcur[3]);

        if (stager) {
            buf[1][rr][4*c4+0][sq] = 0.5f * vg.x;
            buf[1][rr][4*c4+1][sq] = 0.5f * vg.y;
            buf[1][rr][4*c4+2][sq] = 0.5f * vg.z;
            buf[1][rr][4*c4+3][sq] = 0.5f * vg.w;
            pf += qstride;
        }
    }
    __syncthreads();

    float acc0[4] = {0.f,0.f,0.f,0.f};
    float acc1[4] = {0.f,0.f,0.f,0.f};
    const float4* wv = reinterpret_cast<const float4*>(wts);

    #pragma unroll 1
    for (int j = 0; j < NIT; j++) {
        const int bs = j & 1;
        const int nb = bs ^ 1;

        // prefetch quad j+2
        float4 vg;
        const bool ds = stager && (j + 2 < NIT);
        if (ds) vg = __ldg(pf);

        // vertical: quad j+1 from buf[nb] -> vnext; edges -> edge[nb]
        float vnext[QPI] = {0.f, 0.f, 0.f, 0.f};
        if (j + 1 < NIT) {
            float4 a  = *reinterpret_cast<const float4*>(&buf[nb][ra][kx][0]);
            float4 bb = *reinterpret_cast<const float4*>(&buf[nb][rb][kx][0]);
            vnext[0] = fmaf(vf, bb.x - a.x, a.x);
            vnext[1] = fmaf(vf, bb.y - a.y, a.y);
            vnext[2] = fmaf(vf, bb.z - a.z, a.z);
            vnext[3] = fmaf(vf, bb.w - a.w, a.w);
            if (lane == 0)
                *reinterpret_cast<float4*>(&edge[nb][w][0][0])
                    = make_float4(vnext[0], vnext[1], vnext[2], vnext[3]);
            if (lane == 31)
                *reinterpret_cast<float4*>(&edge[nb][w][1][0])
                    = make_float4(vnext[0], vnext[1], vnext[2], vnext[3]);
        }

        // horizontal: quad j from vcur + shuffles + edge[bs]
        float4 eL = make_float4(0.f,0.f,0.f,0.f);
        float4 eR = make_float4(0.f,0.f,0.f,0.f);
        if (lane == 0  && xb > 0)
            eL = *reinterpret_cast<const float4*>(&edge[bs][w-1][1][0]);
        if (lane == 31 && xb < 3)
            eR = *reinterpret_cast<const float4*>(&edge[bs][w+1][0][0]);
        const float eLa[4] = {eL.x, eL.y, eL.z, eL.w};
        const float eRa[4] = {eR.x, eR.y, eR.z, eR.w};

        const float4 wA = wv[2*j];
        const float4 wB = wv[2*j+1];
        const float wxa[4] = {wA.x, wA.z, wB.x, wB.z};
        const float wya[4] = {wA.y, wA.w, wB.y, wB.w};

        #pragma unroll
        for (int e = 0; e < QPI; e++) {
            const float vM = vcur[e];
            float vL = __shfl_up_sync(0xFFFFFFFFu, vM, 1);
            if (lane == 0)  vL = (xb == 0) ? vM : eLa[e];
            float vR = __shfl_down_sync(0xFFFFFFFFu, vM, 1);
            if (lane == 31) vR = (xb == 3) ? vM : eRa[e];

            const float dl = vM - vL;
            const float dr = vR - vM;
            float t0 = fast_tanh(fmaf(0.625f, dl, vL));
            float t1 = fast_tanh(fmaf(0.875f, dl, vL));
            float t2 = fast_tanh(fmaf(0.125f, dr, vM));
            float t3 = fast_tanh(fmaf(0.375f, dr, vM));

            const float wx = wxa[e], wy = wya[e];
            acc0[0] = fmaf(wx, t0, acc0[0]);
            acc0[1] = fmaf(wx, t1, acc0[1]);
            acc0[2] = fmaf(wx, t2, acc0[2]);
            acc0[3] = fmaf(wx, t3, acc0[3]);
            acc1[0] = fmaf(wy, t0, acc1[0]);
            acc1[1] = fmaf(wy, t1, acc1[1]);
            acc1[2] = fmaf(wy, t2, acc1[2]);
            acc1[3] = fmaf(wy, t3, acc1[3]);
        }

        // stage quad j+2 -> buf[bs]
        if (ds) {
            buf[bs][rr][4*c4+0][sq] = 0.5f * vg.x;
            buf[bs][rr][4*c4+1][sq] = 0.5f * vg.y;
            buf[bs][rr][4*c4+2][sq] = 0.5f * vg.z;
            buf[bs][rr][4*c4+3][sq] = 0.5f * vg.w;
            pf += qstride;
        }
        __syncthreads();

        vcur[0] = vnext[0]; vcur[1] = vnext[1];
        vcur[2] = vnext[2]; vcur[3] = vnext[3];
    }

    // out[b][c][4k+ph][4kx + 0..3] = acc + Sum(w/2)
    const float2 S = wsum;
    const int y = 4 * k + ph;
    float4 o0 = make_float4(acc0[0] + S.x, acc0[1] + S.x,
                            acc0[2] + S.x, acc0[3] + S.x);
    float4 o1 = make_float4(acc1[0] + S.y, acc1[1] + S.y,
                            acc1[2] + S.y, acc1[3] + S.y);
    const size_t base0 = (((size_t)b * 2 + 0) * OH + y) * OW + 4 * kx;
    const size_t base1 = (((size_t)b * 2 + 1) * OH + y) * OW + 4 * kx;
    *reinterpret_cast<float4*>(out + base0) = o0;
    *reinterpret_cast<float4*>(out + base1) = o1;
}

extern "C" void kernel_launch(void* const* d_in, const int* in_sizes, int n_in,
                              void* d_out, int out_size)
{
    const float* cls   = (const float*)d_in[0];  // [8,100,3]
    const float* masks = (const float*)d_in[1];  // [8,100,128,128]
    float*       out   = (float*)d_out;          // [8,2,512,512]

    dim3 grid(SH, NB);
    dim3 block(512);
    m2f_fused_kernel<<<grid, block>>>(cls, masks, out);
}

// round 11
// speedup vs baseline: 1.0002x; 1.0002x over previous
#include <cuda_runtime.h>
#include <cstddef>

#define NB   8
#define NQ   100
#define SH   128
#define SW   128
#define OH   512
#define OW   512
#define QPI  4            // queries per iteration
#define NIT  (NQ / QPI)   // 25

__device__ __forceinline__ float fast_tanh(float x) {
    float r;
    asm("tanh.approx.f32 %0, %1;" : "=f"(r) : "f"(x));
    return r;
}

// Grid: (128 row-blocks k, 8 batches). Block: 512 threads, 3 CTAs/SM.
// Register-resident vertical lerp + shuffle-based horizontal neighbors.
// Thread role: ph = t>>7 (row phase), kx = t&127 (source column).
//   iter j: horizontal(quad j from vcur regs + edge[bs])
//        || vertical(quad j+1 from buf -> vnext regs, lane0/31 -> edge[nb])
//        || stage(quad j+2 -> buf[bs]);  ONE __syncthreads.
// buf layout [slot][row][col][e] -> vertical reads are 2x LDS.128.
// Data pre-halved; weights pre-halved; +Sum(w/2) folded at the end.
__global__ __launch_bounds__(512, 3)
void m2f_fused_kernel(const float* __restrict__ cls,
                      const float* __restrict__ masks,
                      float* __restrict__ out)
{
    const int k = blockIdx.x;
    const int b = blockIdx.y;
    const int t = threadIdx.x;

    __shared__ __align__(16) float buf[2][3][SW][QPI];   // staged rows, e-interleaved
    __shared__ __align__(16) float edge[2][16][2][QPI];  // [slot][warp][lo/hi][e]
    __shared__ __align__(16) float2 wts[NQ];
    __shared__ float2 wsum;

    const int lane = t & 31;
    const int w    = t >> 5;       // warp 0..15
    const int xb   = w & 3;        // x-block of warp within its phase
    const int ph   = t >> 7;       // row phase 0..3
    const int kx   = t & 127;      // source column

    // ---- per-CTA class softmax (halved) ----
    if (t < NQ) {
        const float* p = cls + ((size_t)b * NQ + t) * 3;
        float x0 = p[0], x1 = p[1], x2 = p[2];
        float m  = fmaxf(x0, fmaxf(x1, x2));
        float e0 = __expf(x0 - m), e1 = __expf(x1 - m), e2 = __expf(x2 - m);
        float inv = 0.5f / (e0 + e1 + e2);
        wts[t] = make_float2(e0 * inv, e1 * inv);
    }

    // clamped source rows
    const int r0 = (k == 0)      ? 0        : (k - 1);
    const int r2 = (k == SH - 1) ? (SH - 1) : (k + 1);
    const float* mb = masks + (size_t)b * NQ * SH * SW;
    const size_t qstride = (size_t)SH * SW;

    // staging role: 384 threads (warps 0..11), one float4 each
    const bool stager = (t < 384);
    const int  sq = w / 3;             // query-in-quad 0..3
    const int  rr = w % 3;             // row 0..2
    const int  c4 = t & 31;
    const int  stg_row = (rr == 0) ? r0 : ((rr == 1) ? k : r2);
    const float4* pf = reinterpret_cast<const float4*>(
        mb + (size_t)sq * qstride + (size_t)stg_row * SW) + c4;

    // vertical factors per phase
    const int ra   = (ph < 2) ? 0 : 1;
    const int rb   = ra + 1;
    const float vf = (ph == 0) ? 0.625f : (ph == 1) ? 0.875f
                   : (ph == 2) ? 0.125f : 0.375f;

    // ---- prologue: stage quad 0 ----
    if (stager) {
        float4 v = __ldg(pf);
        buf[0][rr][4*c4+0][sq] = 0.5f * v.x;
        buf[0][rr][4*c4+1][sq] = 0.5f * v.y;
        buf[0][rr][4*c4+2][sq] = 0.5f * v.z;
        buf[0][rr][4*c4+3][sq] = 0.5f * v.w;
        pf += qstride;   // float4 units: 4 queries ahead
    }
    __syncthreads();   // wts + buf[0] visible

    // weight sum (halved) by warp 0
    if (t < 32) {
        float sx = 0.f, sy = 0.f;
        for (int q = t; q < NQ; q += 32) { sx += wts[q].x; sy += wts[q].y; }
        #pragma unroll
        for (int o = 16; o > 0; o >>= 1) {
            sx += __shfl_down_sync(0xFFFFFFFFu, sx, o);
            sy += __shfl_down_sync(0xFFFFFFFFu, sy, o);
        }
        if (t == 0) wsum = make_float2(sx, sy);
    }

    // ---- prologue: vertical quad 0 -> vcur; stage quad 1 -> buf[1] ----
    float vcur[QPI];
    {
        float4 vg;
        if (stager) vg = __ldg(pf);

        float4 a  = *reinterpret_cast<const float4*>(&buf[0][ra][kx][0]);
        float4 bb = *reinterpret_cast<const float4*>(&buf[0][rb][kx][0]);
        vcur[0] = fmaf(vf, bb.x - a.x, a.x);
        vcur[1] = fmaf(vf, bb.y - a.y, a.y);
        vcur[2] = fmaf(vf, bb.z - a.z, a.z);
        vcur[3] = fmaf(vf, bb.w - a.w, a.w);
        if (lane == 0)
            *reinterpret_cast<float4*>(&edge[0][w][0][0])
                = make_float4(vcur[0], vcur[1], vcur[2], vcur[3]);
        if (lane == 31)
            *reinterpret_cast<float4*>(&edge[0][w][1][0])
                = make_float4(vcur[0], vcur[1], vcur[2], vcur[3]);

        if (stager) {
            buf[1][rr][4*c4+0][sq] = 0.5f * vg.x;
            buf[1][rr][4*c4+1][sq] = 0.5f * vg.y;
            buf[1][rr][4*c4+2][sq] = 0.5f * vg.z;
            buf[1][rr][4*c4+3][sq] = 0.5f * vg.w;
            pf += qstride;
        }
    }
    __syncthreads();

    float acc0[4] = {0.f,0.f,0.f,0.f};
    float acc1[4] = {0.f,0.f,0.f,0.f};
    const float4* wv = reinterpret_cast<const float4*>(wts);

    #pragma unroll 1
    for (int j = 0; j < NIT; j++) {
        const int bs = j & 1;
        const int nb = bs ^ 1;

        // prefetch quad j+2
        float4 vg;
        const bool ds = stager && (j + 2 < NIT);
        if (ds) vg = __ldg(pf);

        // vertical: quad j+1 from buf[nb] -> vnext; edges -> edge[nb]
        float vnext[QPI] = {0.f, 0.f, 0.f, 0.f};
        if (j + 1 < NIT) {
            float4 a  = *reinterpret_cast<const float4*>(&buf[nb][ra][kx][0]);
            float4 bb = *reinterpret_cast<const float4*>(&buf[nb][rb][kx][0]);
            vnext[0] = fmaf(vf, bb.x - a.x, a.x);
            vnext[1] = fmaf(vf, bb.y - a.y, a.y);
            vnext[2] = fmaf(vf, bb.z - a.z, a.z);
            vnext[3] = fmaf(vf, bb.w - a.w, a.w);
            if (lane == 0)
                *reinterpret_cast<float4*>(&edge[nb][w][0][0])
                    = make_float4(vnext[0], vnext[1], vnext[2], vnext[3]);
            if (lane == 31)
                *reinterpret_cast<float4*>(&edge[nb][w][1][0])
                    = make_float4(vnext[0], vnext[1], vnext[2], vnext[3]);
        }

        // horizontal: quad j from vcur + shuffles + edge[bs]
        float4 eL = make_float4(0.f,0.f,0.f,0.f);
        float4 eR = make_float4(0.f,0.f,0.f,0.f);
        if (lane == 0  && xb > 0)
            eL = *reinterpret_cast<const float4*>(&edge[bs][w-1][1][0]);
        if (lane == 31 && xb < 3)
            eR = *reinterpret_cast<const float4*>(&edge[bs][w+1][0][0]);
        const float eLa[4] = {eL.x, eL.y, eL.z, eL.w};
        const float eRa[4] = {eR.x, eR.y, eR.z, eR.w};

        const float4 wA = wv[2*j];
        const float4 wB = wv[2*j+1];
        const float wxa[4] = {wA.x, wA.z, wB.x, wB.z};
        const float wya[4] = {wA.y, wA.w, wB.y, wB.w};

        #pragma unroll
        for (int e = 0; e < QPI; e++) {
            const float vM = vcur[e];
            float vL = __shfl_up_sync(0xFFFFFFFFu, vM, 1);
            if (lane == 0)  vL = (xb == 0) ? vM : eLa[e];
            float vR = __shfl_down_sync(0xFFFFFFFFu, vM, 1);
            if (lane == 31) vR = (xb == 3) ? vM : eRa[e];

            const float dl = vM - vL;
            const float dr = vR - vM;
            float t0 = fast_tanh(fmaf(0.625f, dl, vL));
            float t1 = fast_tanh(fmaf(0.875f, dl, vL));
            float t2 = fast_tanh(fmaf(0.125f, dr, vM));
            float t3 = fast_tanh(fmaf(0.375f, dr, vM));

            const float wx = wxa[e], wy = wya[e];
            acc0[0] = fmaf(wx, t0, acc0[0]);
            acc0[1] = fmaf(wx, t1, acc0[1]);
            acc0[2] = fmaf(wx, t2, acc0[2]);
            acc0[3] = fmaf(wx, t3, acc0[3]);
            acc1[0] = fmaf(wy, t0, acc1[0]);
            acc1[1] = fmaf(wy, t1, acc1[1]);
            acc1[2] = fmaf(wy, t2, acc1[2]);
            acc1[3] = fmaf(wy, t3, acc1[3]);
        }

        // stage quad j+2 -> buf[bs]
        if (ds) {
            buf[bs][rr][4*c4+0][sq] = 0.5f * vg.x;
            buf[bs][rr][4*c4+1][sq] = 0.5f * vg.y;
            buf[bs][rr][4*c4+2][sq] = 0.5f * vg.z;
            buf[bs][rr][4*c4+3][sq] = 0.5f * vg.w;
            pf += qstride;
        }
        __syncthreads();

        vcur[0] = vnext[0]; vcur[1] = vnext[1];
        vcur[2] = vnext[2]; vcur[3] = vnext[3];
    }

    // out[b][c][4k+ph][4kx + 0..3] = acc + Sum(w/2)
    const float2 S = wsum;
    const int y = 4 * k + ph;
    float4 o0 = make_float4(acc0[0] + S.x, acc0[1] + S.x,
                            acc0[2] + S.x, acc0[3] + S.x);
    float4 o1 = make_float4(acc1[0] + S.y, acc1[1] + S.y,
                            acc1[2] + S.y, acc1[3] + S.y);
    const size_t base0 = (((size_t)b * 2 + 0) * OH + y) * OW + 4 * kx;
    const size_t base1 = (((size_t)b * 2 + 1) * OH + y) * OW + 4 * kx;
    *reinterpret_cast<float4*>(out + base0) = o0;
    *reinterpret_cast<float4*>(out + base1) = o1;
}

extern "C" void kernel_launch(void* const* d_in, const int* in_sizes, int n_in,
                              void* d_out, int out_size)
{
    const float* cls   = (const float*)d_in[0];  // [8,100,3]
    const float* masks = (const float*)d_in[1];  // [8,100,128,128]
    float*       out   = (float*)d_out;          // [8,2,512,512]

    dim3 grid(SH, NB);
    dim3 block(512);
    m2f_fused_kernel<<<grid, block>>>(cls, masks, out);
}

// round 12
// speedup vs baseline: 1.7977x; 1.7973x over previous
#include <cuda_runtime.h>
#include <cstddef>

#define NB   8
#define NQ   100
#define SH   128
#define SW   128
#define OH   512
#define OW   512
#define QPI  4            // queries per iteration
#define NIT  (NQ / QPI)   // 25

__device__ __forceinline__ float fast_tanh(float x) {
    float r;
    asm("tanh.approx.f32 %0, %1;" : "=f"(r) : "f"(x));
    return r;
}

// Grid: (128 row-blocks k, 8 batches). Block: 512 threads, 3 CTAs/SM.
// R9 pipeline (one __syncthreads per iteration):
//   iter j: horizontal(quad j from vrow4[j&1]) || vertical(quad j+1 -> vrow4[~])
//           || stage(quad j+2 -> buf[j&1])
// vrow is e-innermost float4 -> vertical writes 1 STS.128, horizontal reads
// 3 LDS.128 (vs 4 STS.32 + 12 LDS.32 in R9). buf stays per-e contiguous so
// staging remains conflict-free float4.
__global__ __launch_bounds__(512, 3)
void m2f_fused_kernel(const float* __restrict__ cls,
                      const float* __restrict__ masks,
                      float* __restrict__ out)
{
    const int k = blockIdx.x;
    const int b = blockIdx.y;
    const int t = threadIdx.x;

    __shared__ __align__(16) float  buf[2][QPI][3][SW];  // staged rows (halved)
    __shared__ __align__(16) float4 vrow4[2][4][SW];     // [slot][ph][col] = 4 e's
    __shared__ __align__(16) float2 wts[NQ];
    __shared__ float2 wsum;

    // ---- per-CTA class softmax (halved) ----
    if (t < NQ) {
        const float* p = cls + ((size_t)b * NQ + t) * 3;
        float x0 = p[0], x1 = p[1], x2 = p[2];
        float m  = fmaxf(x0, fmaxf(x1, x2));
        float e0 = __expf(x0 - m), e1 = __expf(x1 - m), e2 = __expf(x2 - m);
        float inv = 0.5f / (e0 + e1 + e2);
        wts[t] = make_float2(e0 * inv, e1 * inv);
    }

    // clamped source rows
    const int r0 = (k == 0)      ? 0        : (k - 1);
    const int r2 = (k == SH - 1) ? (SH - 1) : (k + 1);
    const float* mb = masks + (size_t)b * NQ * SH * SW;
    const size_t qstride = (size_t)SH * SW;

    // staging role: 384 threads (warps 0..11), one float4 each
    const bool stager = (t < 384);
    const int  w  = t >> 5;
    const int  sq = w / 3;             // query-in-quad 0..3
    const int  rr = w % 3;             // row 0..2
    const int  c4 = t & 31;
    const int  stg_row = (rr == 0) ? r0 : ((rr == 1) ? k : r2);
    const float4* pf = reinterpret_cast<const float4*>(
        mb + (size_t)sq * qstride + (size_t)stg_row * SW) + c4;

    // role: ph = t>>7 (row phase), kx = t&127 (source column) for BOTH stages
    const int ph  = t >> 7;
    const int kx  = t & 127;
    const int ra  = (ph < 2) ? 0 : 1;
    const int rb  = ra + 1;
    const float vf = (ph == 0) ? 0.625f : (ph == 1) ? 0.875f
                   : (ph == 2) ? 0.125f : 0.375f;
    const int kxm = (kx == 0)      ? 0        : kx - 1;
    const int kxp = (kx == SW - 1) ? (SW - 1) : kx + 1;

    // ---- prologue: stage quad 0 ----
    if (stager) {
        float4 v = __ldg(pf);
        v.x *= 0.5f; v.y *= 0.5f; v.z *= 0.5f; v.w *= 0.5f;
        reinterpret_cast<float4*>(&buf[0][sq][rr][0])[c4] = v;
        pf += qstride;   // float4 units: 4 queries ahead
    }
    __syncthreads();   // wts + buf[0] visible

    // weight sum (halved) by warp 0
    if (t < 32) {
        float sx = 0.f, sy = 0.f;
        for (int q = t; q < NQ; q += 32) { sx += wts[q].x; sy += wts[q].y; }
        #pragma unroll
        for (int o = 16; o > 0; o >>= 1) {
            sx += __shfl_down_sync(0xFFFFFFFFu, sx, o);
            sy += __shfl_down_sync(0xFFFFFFFFu, sy, o);
        }
        if (t == 0) wsum = make_float2(sx, sy);
    }

    // ---- prologue: vertical quad 0 -> vrow4[0]; stage quad 1 -> buf[1] ----
    {
        float4 vg;
        if (stager) vg = __ldg(pf);

        float r[QPI];
        #pragma unroll
        for (int e = 0; e < QPI; e++) {
            float a  = buf[0][e][ra][kx];
            float bb = buf[0][e][rb][kx];
            r[e] = fmaf(vf, bb - a, a);
        }
        vrow4[0][ph][kx] = make_float4(r[0], r[1], r[2], r[3]);

        if (stager) {
            vg.x *= 0.5f; vg.y *= 0.5f; vg.z *= 0.5f; vg.w *= 0.5f;
            reinterpret_cast<float4*>(&buf[1][sq][rr][0])[c4] = vg;
            pf += qstride;
        }
    }
    __syncthreads();

    float acc0[4] = {0.f,0.f,0.f,0.f};
    float acc1[4] = {0.f,0.f,0.f,0.f};
    const float4* wv = reinterpret_cast<const float4*>(wts);

    #pragma unroll 1
    for (int j = 0; j < NIT; j++) {
        const int bs = j & 1;
        const int nb = bs ^ 1;

        // prefetch quad j+2
        float4 vg;
        const bool ds = stager && (j + 2 < NIT);
        if (ds) vg = __ldg(pf);

        // vertical: quad j+1 from buf[nb] -> vrow4[nb]
        if (j + 1 < NIT) {
            float r[QPI];
            #pragma unroll
            for (int e = 0; e < QPI; e++) {
                float a  = buf[nb][e][ra][kx];
                float bb = buf[nb][e][rb][kx];
                r[e] = fmaf(vf, bb - a, a);
            }
            vrow4[nb][ph][kx] = make_float4(r[0], r[1], r[2], r[3]);
        }

        // horizontal: quad j from vrow4[bs]  (3x LDS.128)
        {
            const float4 L4 = vrow4[bs][ph][kxm];
            const float4 M4 = vrow4[bs][ph][kx];
            const float4 R4 = vrow4[bs][ph][kxp];
            const float La[4] = {L4.x, L4.y, L4.z, L4.w};
            const float Ma[4] = {M4.x, M4.y, M4.z, M4.w};
            const float Ra[4] = {R4.x, R4.y, R4.z, R4.w};

            const float4 wA = wv[2*j];
            const float4 wB = wv[2*j+1];
            const float wxa[4] = {wA.x, wA.z, wB.x, wB.z};
            const float wya[4] = {wA.y, wA.w, wB.y, wB.w};

            #pragma unroll
            for (int e = 0; e < QPI; e++) {
                const float vL = La[e], vM = Ma[e], vR = Ra[e];
                const float dl = vM - vL;
                const float dr = vR - vM;

                float t0 = fast_tanh(fmaf(0.625f, dl, vL));
                float t1 = fast_tanh(fmaf(0.875f, dl, vL));
                float t2 = fast_tanh(fmaf(0.125f, dr, vM));
                float t3 = fast_tanh(fmaf(0.375f, dr, vM));

                const float wx = wxa[e], wy = wya[e];
                acc0[0] = fmaf(wx, t0, acc0[0]);
                acc0[1] = fmaf(wx, t1, acc0[1]);
                acc0[2] = fmaf(wx, t2, acc0[2]);
                acc0[3] = fmaf(wx, t3, acc0[3]);
                acc1[0] = fmaf(wy, t0, acc1[0]);
                acc1[1] = fmaf(wy, t1, acc1[1]);
                acc1[2] = fmaf(wy, t2, acc1[2]);
                acc1[3] = fmaf(wy, t3, acc1[3]);
            }
        }

        // stage quad j+2 -> buf[bs]
        if (ds) {
            vg.x *= 0.5f; vg.y *= 0.5f; vg.z *= 0.5f; vg.w *= 0.5f;
            reinterpret_cast<float4*>(&buf[bs][sq][rr][0])[c4] = vg;
            pf += qstride;
        }
        __syncthreads();
    }

    // out[b][c][4k+ph][4kx + 0..3] = acc + Sum(w/2)
    const float2 S = wsum;
    const int y = 4 * k + ph;
    float4 o0 = make_float4(acc0[0] + S.x, acc0[1] + S.x,
                            acc0[2] + S.x, acc0[3] + S.x);
    float4 o1 = make_float4(acc1[0] + S.y, acc1[1] + S.y,
                            acc1[2] + S.y, acc1[3] + S.y);
    const size_t base0 = (((size_t)b * 2 + 0) * OH + y) * OW + 4 * kx;
    const size_t base1 = (((size_t)b * 2 + 1) * OH + y) * OW + 4 * kx;
    *reinterpret_cast<float4*>(out + base0) = o0;
    *reinterpret_cast<float4*>(out + base1) = o1;
}

extern "C" void kernel_launch(void* const* d_in, const int* in_sizes, int n_in,
                              void* d_out, int out_size)
{
    const float* cls   = (const float*)d_in[0];  // [8,100,3]
    const float* masks = (const float*)d_in[1];  // [8,100,128,128]
    float*       out   = (float*)d_out;          // [8,2,512,512]

    dim3 grid(SH, NB);
    dim3 block(512);
    m2f_fused_kernel<<<grid, block>>>(cls, masks, out);
}

// round 14
// speedup vs baseline: 2.1881x; 1.2172x over previous
#include <cuda_runtime.h>
#include <cstddef>

#define NB   8
#define NQ   100
#define SH   128
#define SW   128
#define OH   512
#define OW   512
#define QPI  4            // queries per iteration
#define NIT  (NQ / QPI)   // 25

__device__ __forceinline__ float fast_tanh(float x) {
    float r;
    asm("tanh.approx.f32 %0, %1;" : "=f"(r) : "f"(x));
    return r;
}

// Grid: (128 row-blocks k, 8 batches). Block: 512 threads, 3 CTAs/SM.
// NO staging buffer: vertical stage reads source rows straight from GMEM.
//   warp w owns (e = w&3, ph = w>>2): 2x LDG.128 (rows ra,rb of query 4(j+1)+e),
//   lerp+halve, 1x STS.128 into vrow[(j+1)&1][e][ph][...].
//   horizontal(quad j) reads vrow[j&1][e][ph][kx-1,kx,kx+1] (conflict-free LDS.32).
// ONE __syncthreads per iteration. Weights pre-halved; +Sum(w/2) folded at end.
// R13 bug fixed: weight-sum reduction now runs AFTER the sync publishing wts.
__global__ __launch_bounds__(512, 3)
void m2f_fused_kernel(const float* __restrict__ cls,
                      const float* __restrict__ masks,
                      float* __restrict__ out)
{
    const int k = blockIdx.x;
    const int b = blockIdx.y;
    const int t = threadIdx.x;

    __shared__ __align__(16) float  vrow[2][QPI][4][SW];  // halved vertical lerps
    __shared__ __align__(16) float2 wts[NQ];              // pre-halved weights
    __shared__ float2 wsum;

    // ---- per-CTA class softmax (halved) ----
    if (t < NQ) {
        const float* p = cls + ((size_t)b * NQ + t) * 3;
        float x0 = p[0], x1 = p[1], x2 = p[2];
        float m  = fmaxf(x0, fmaxf(x1, x2));
        float e0 = __expf(x0 - m), e1 = __expf(x1 - m), e2 = __expf(x2 - m);
        float inv = 0.5f / (e0 + e1 + e2);
        wts[t] = make_float2(e0 * inv, e1 * inv);
    }

    // clamped source rows
    const int r0 = (k == 0)      ? 0        : (k - 1);
    const int r2 = (k == SH - 1) ? (SH - 1) : (k + 1);
    const float* mb = masks + (size_t)b * NQ * SH * SW;
    const size_t qstride = (size_t)SH * SW;     // floats per query
    const size_t qf4     = qstride / 4;         // float4s per query

    // shared role keys: ph = t>>7 (row phase), kx = t&127
    const int ph  = t >> 7;
    const int kx  = t & 127;
    const float vf = (ph == 0) ? 0.625f : (ph == 1) ? 0.875f
                   : (ph == 2) ? 0.125f : 0.375f;
    const int rowA = (ph < 2) ? r0 : k;
    const int rowB = (ph < 2) ? k  : r2;
    const int kxm = (kx == 0)      ? 0        : kx - 1;
    const int kxp = (kx == SW - 1) ? (SW - 1) : kx + 1;

    // vertical role: warp w -> (e = w&3, ph = w>>2); lane -> 4-col group
    const int wid = t >> 5;
    const int ev  = wid & 3;
    const int c4g = t & 31;
    const float4* pA = reinterpret_cast<const float4*>(
        mb + (size_t)ev * qstride + (size_t)rowA * SW) + c4g;
    const float4* pB = reinterpret_cast<const float4*>(
        mb + (size_t)ev * qstride + (size_t)rowB * SW) + c4g;

    // ---- prologue: vertical quad 0 -> vrow[0] ----
    {
        float4 la = __ldg(pA);
        float4 lb = __ldg(pB);
        float4 r;
        r.x = 0.5f * fmaf(vf, lb.x - la.x, la.x);
        r.y = 0.5f * fmaf(vf, lb.y - la.y, la.y);
        r.z = 0.5f * fmaf(vf, lb.z - la.z, la.z);
        r.w = 0.5f * fmaf(vf, lb.w - la.w, la.w);
        *reinterpret_cast<float4*>(&vrow[0][ev][ph][4 * c4g]) = r;
        pA += QPI * qf4;
        pB += QPI * qf4;
    }

    __syncthreads();   // wts + vrow[0] published

    // weight sum (halved) by warp 0 — AFTER wts is published (R13 raced here).
    // wsum write is ordered before the end-of-kernel reads by the loop's syncs.
    if (t < 32) {
        float sx = 0.f, sy = 0.f;
        for (int q = t; q < NQ; q += 32) { sx += wts[q].x; sy += wts[q].y; }
        #pragma unroll
        for (int o = 16; o > 0; o >>= 1) {
            sx += __shfl_down_sync(0xFFFFFFFFu, sx, o);
            sy += __shfl_down_sync(0xFFFFFFFFu, sy, o);
        }
        if (t == 0) wsum = make_float2(sx, sy);
    }

    float acc0[4] = {0.f,0.f,0.f,0.f};
    float acc1[4] = {0.f,0.f,0.f,0.f};
    const float4* wv = reinterpret_cast<const float4*>(wts);

    #pragma unroll 2
    for (int j = 0; j < NIT; j++) {
        const int bs = j & 1;
        const int nb = bs ^ 1;

        // issue LDG for quad j+1 first (hidden under horizontal compute)
        float4 la, lb;
        const bool dv = (j + 1 < NIT);
        if (dv) {
            la = __ldg(pA);
            lb = __ldg(pB);
        }

        // horizontal: quad j from vrow[bs]
        {
            const float4 wA = wv[2*j];
            const float4 wB = wv[2*j+1];
            const float wxa[4] = {wA.x, wA.z, wB.x, wB.z};
            const float wya[4] = {wA.y, wA.w, wB.y, wB.w};

            #pragma unroll
            for (int e = 0; e < QPI; e++) {
                const float vL = vrow[bs][e][ph][kxm];
                const float vM = vrow[bs][e][ph][kx];
                const float vR = vrow[bs][e][ph][kxp];
                const float dl = vM - vL;
                const float dr = vR - vM;

                float t0 = fast_tanh(fmaf(0.625f, dl, vL));
                float t1 = fast_tanh(fmaf(0.875f, dl, vL));
                float t2 = fast_tanh(fmaf(0.125f, dr, vM));
                float t3 = fast_tanh(fmaf(0.375f, dr, vM));

                const float wx = wxa[e], wy = wya[e];
                acc0[0] = fmaf(wx, t0, acc0[0]);
                acc0[1] = fmaf(wx, t1, acc0[1]);
                acc0[2] = fmaf(wx, t2, acc0[2]);
                acc0[3] = fmaf(wx, t3, acc0[3]);
                acc1[0] = fmaf(wy, t0, acc1[0]);
                acc1[1] = fmaf(wy, t1, acc1[1]);
                acc1[2] = fmaf(wy, t2, acc1[2]);
                acc1[3] = fmaf(wy, t3, acc1[3]);
            }
        }

        // vertical: quad j+1 -> vrow[nb]
        if (dv) {
            float4 r;
            r.x = 0.5f * fmaf(vf, lb.x - la.x, la.x);
            r.y = 0.5f * fmaf(vf, lb.y - la.y, la.y);
            r.z = 0.5f * fmaf(vf, lb.z - la.z, la.z);
            r.w = 0.5f * fmaf(vf, lb.w - la.w, la.w);
            *reinterpret_cast<float4*>(&vrow[nb][ev][ph][4 * c4g]) = r;
            pA += QPI * qf4;
            pB += QPI * qf4;
        }
        __syncthreads();
    }

    // out[b][c][4k+ph][4kx + 0..3] = acc + Sum(w/2)
    const float2 S = wsum;
    const int y = 4 * k + ph;
    float4 o0 = make_float4(acc0[0] + S.x, acc0[1] + S.x,
                            acc0[2] + S.x, acc0[3] + S.x);
    float4 o1 = make_float4(acc1[0] + S.y, acc1[1] + S.y,
                            acc1[2] + S.y, acc1[3] + S.y);
    const size_t base0 = (((size_t)b * 2 + 0) * OH + y) * OW + 4 * kx;
    const size_t base1 = (((size_t)b * 2 + 1) * OH + y) * OW + 4 * kx;
    *reinterpret_cast<float4*>(out + base0) = o0;
    *reinterpret_cast<float4*>(out + base1) = o1;
}

extern "C" void kernel_launch(void* const* d_in, const int* in_sizes, int n_in,
                              void* d_out, int out_size)
{
    const float* cls   = (const float*)d_in[0];  // [8,100,3]
    const float* masks = (const float*)d_in[1];  // [8,100,128,128]
    float*       out   = (float*)d_out;          // [8,2,512,512]

    dim3 grid(SH, NB);
    dim3 block(512);
    m2f_fused_kernel<<<grid, block>>>(cls, masks, out);
}